// round 12
// baseline (speedup 1.0000x reference)
#include <cuda_runtime.h>
#include <cuda_fp16.h>

#define N_USERS 50000
#define NN      100000        // total nodes
#define EMBED   64
#define FDIM    192           // 3 streams interleaved: [e | img | txt]
#define NEDGES  1600000
#define BATCH   4096
#define CAT_RATE 0.02f

// ---------------- device scratch ----------------------------------------------
__device__ __half g_F0[NN * FDIM];
__device__ __half g_F1[NN * FDIM];
__device__ __half g_F2[NN * FDIM];
__device__ int           g_count[NN];       // zero at load; re-zeroed each launch
__device__ int           g_rowstart[NN + 1];
__device__ unsigned char g_rank8[NEDGES];   // within-row rank (max deg << 256)
__device__ int           g_needflag[NN];    // rows needing F2; re-zeroed each launch
__device__ int2          g_edge[NEDGES];    // (col, val-as-int-bits), row-grouped
__device__ int           g_blocksums[256];
__device__ volatile int  g_scanflag[256];   // lookback flags; re-zeroed each launch

// ---------------- pure hist (+packed rank), 8 edges/thread ---------------------
#define NB_HIST ((NEDGES / 8 + 255) / 256)      // 782

__global__ void k_hist(const int* __restrict__ rows) {
    int e8 = (blockIdx.x * blockDim.x + threadIdx.x) * 8;
    if (e8 < NEDGES) {
        int4 ra = *(const int4*)(rows + e8);
        int4 rb = *(const int4*)(rows + e8 + 4);
        unsigned int k0 = atomicAdd(&g_count[ra.x], 1);
        unsigned int k1 = atomicAdd(&g_count[ra.y], 1);
        unsigned int k2 = atomicAdd(&g_count[ra.z], 1);
        unsigned int k3 = atomicAdd(&g_count[ra.w], 1);
        unsigned int k4 = atomicAdd(&g_count[rb.x], 1);
        unsigned int k5 = atomicAdd(&g_count[rb.y], 1);
        unsigned int k6 = atomicAdd(&g_count[rb.z], 1);
        unsigned int k7 = atomicAdd(&g_count[rb.w], 1);
        uint2 packed;
        packed.x = (k0 & 0xFF) | ((k1 & 0xFF) << 8) | ((k2 & 0xFF) << 16) | ((k3 & 0xFF) << 24);
        packed.y = (k4 & 0xFF) | ((k5 & 0xFF) << 8) | ((k6 & 0xFF) << 16) | ((k7 & 0xFF) << 24);
        *(uint2*)(g_rank8 + e8) = packed;
    }
}

// ---------------- single-pass scan with decoupled lookback ---------------------
// 196 blocks, all co-resident (196 < 148*4) -> spin-wait is deadlock-free.
#define SCAN_T 512
#define SCAN_NB ((NN + SCAN_T - 1) / SCAN_T)   // 196

__global__ void k_scan() {
    __shared__ int sm[SCAN_T];
    __shared__ int s_off;
    int b = blockIdx.x;
    int i = b * SCAN_T + threadIdx.x;
    int v = (i < NN) ? g_count[i] : 0;
    sm[threadIdx.x] = v;
    __syncthreads();
    // local Hillis-Steele inclusive scan
    for (int off = 1; off < SCAN_T; off <<= 1) {
        int add = (threadIdx.x >= off) ? sm[threadIdx.x - off] : 0;
        __syncthreads();
        sm[threadIdx.x] += add;
        __syncthreads();
    }
    int incl = sm[threadIdx.x];
    // publish block total
    if (threadIdx.x == SCAN_T - 1) {
        g_blocksums[b] = incl;
        __threadfence();
        g_scanflag[b] = 1;
    }
    // lookback: sum totals of predecessor blocks (spin until published)
    int contrib = 0;
    for (int j = threadIdx.x; j < b; j += SCAN_T) {
        while (g_scanflag[j] == 0) { }
        contrib += g_blocksums[j];
    }
    __syncthreads();           // reuse sm for reduction
    sm[threadIdx.x] = contrib;
    __syncthreads();
    for (int off = SCAN_T / 2; off > 0; off >>= 1) {
        if (threadIdx.x < off) sm[threadIdx.x] += sm[threadIdx.x + off];
        __syncthreads();
    }
    if (threadIdx.x == 0) s_off = sm[0];
    __syncthreads();
    int excl = incl - v + s_off;
    if (i < NN) g_rowstart[i] = excl;
    if (i == 0) g_rowstart[NN] = NEDGES;
}

// ---------------- fused: scatter (4 edges/thread) + feature init, 1:9 stripe ---
#define NB_SCAT  ((NEDGES / 4 + 255) / 256)      // 1563
#define NB_INITE ((NN * EMBED / 4 + 255) / 256)  // 6250
#define NB_TILES (NN / 32)                       // 3125
#define NB_INIT  (NB_INITE + 2 * NB_TILES)       // 12500
#define SI_GRID  (NB_SCAT * 9)                   // 14067: g%9==0 -> scatter

__global__ void k_scatter_init(const int* __restrict__ rows, const int* __restrict__ cols,
                               const float* __restrict__ vals,
                               const float* __restrict__ E0,
                               const float* __restrict__ Wimg,
                               const float* __restrict__ Wtxt) {
    __shared__ float sm[64][33];
    int g = blockIdx.x;
    if (g % 9 == 0) {
        int sb = g / 9;                          // 0..1562
        int e4 = (sb * 256 + threadIdx.x) * 4;
        if (e4 < NEDGES) {
            int4   r4 = *(const int4*)(rows + e4);
            int4   c4 = *(const int4*)(cols + e4);
            float4 v4 = *(const float4*)(vals + e4);
            unsigned int kk = *(const unsigned int*)(g_rank8 + e4);
            g_edge[g_rowstart[r4.x] + ( kk        & 0xFF)] = make_int2(c4.x, __float_as_int(v4.x));
            g_edge[g_rowstart[r4.y] + ((kk >>  8) & 0xFF)] = make_int2(c4.y, __float_as_int(v4.y));
            g_edge[g_rowstart[r4.z] + ((kk >> 16) & 0xFF)] = make_int2(c4.z, __float_as_int(v4.z));
            g_edge[g_rowstart[r4.w] + ((kk >> 24) & 0xFF)] = make_int2(c4.w, __float_as_int(v4.w));
        }
        return;
    }
    int b = g - (g / 9) - 1;                     // contiguous over non-scatter blocks
    if (b >= NB_INIT) return;
    if (b < NB_INITE) {
        int i = b * 256 + threadIdx.x;           // over NN*16 float4s
        if (i < NN * (EMBED / 4)) {
            int n  = i >> 4;
            int d4 = (i & 15) * 4;
            float4 v = ((const float4*)E0)[i];
            __half2* dst = (__half2*)(g_F0 + (size_t)n * FDIM + d4);
            dst[0] = __floats2half2_rn(v.x, v.y);
            dst[1] = __floats2half2_rn(v.z, v.w);
        }
        return;
    }
    b -= NB_INITE;
    const float* W = (b < NB_TILES) ? Wimg : Wtxt;
    int plane_off  = (b < NB_TILES) ? 64 : 128;
    int tile = (b < NB_TILES) ? b : (b - NB_TILES);
    int n0 = tile * 32;
    int tx = threadIdx.x & 31;
    int ty = threadIdx.x >> 5;   // 0..7
    #pragma unroll
    for (int k = 0; k < 8; k++) {
        int d = k * 8 + ty;
        sm[d][tx] = W[(size_t)d * NN + n0 + tx];
    }
    __syncthreads();
    #pragma unroll
    for (int k = 0; k < 4; k++) {
        int row = k * 8 + ty;
        int n = n0 + row;
        #pragma unroll
        for (int dk = 0; dk < 2; dk++) {
            int d = dk * 32 + tx;
            g_F0[(size_t)n * FDIM + plane_off + d] = __float2half_rn(sm[d][row]);
        }
    }
}

// ---------------- SPMM row body (fp16 in/out, fp32 accum) ----------------------
__device__ __forceinline__ void spmm_row(int row, int lane,
                                         const __half* __restrict__ A, __half* __restrict__ B,
                                         const float* __restrict__ bias_i,
                                         const float* __restrict__ bias_t) {
    int s = g_rowstart[row];
    int e = g_rowstart[row + 1];
    float a0 = 0.f, a1 = 0.f, i0 = 0.f, i1 = 0.f, t0 = 0.f, t1 = 0.f;
    int k = s;
    for (; k + 1 < e; k += 2) {
        int2  eA = __ldg(&g_edge[k]);
        int2  eB = __ldg(&g_edge[k + 1]);
        float vA = __int_as_float(eA.y);
        float vB = __int_as_float(eB.y);
        const __half2* xA = (const __half2*)(A + (size_t)eA.x * FDIM);
        const __half2* xB = (const __half2*)(A + (size_t)eB.x * FDIM);
        float2 fA0 = __half22float2(xA[lane]);
        float2 fA1 = __half22float2(xA[32 + lane]);
        float2 fA2 = __half22float2(xA[64 + lane]);
        float2 fB0 = __half22float2(xB[lane]);
        float2 fB1 = __half22float2(xB[32 + lane]);
        float2 fB2 = __half22float2(xB[64 + lane]);
        a0 += vA * fA0.x; a1 += vA * fA0.y;
        i0 += vA * fA1.x; i1 += vA * fA1.y;
        t0 += vA * fA2.x; t1 += vA * fA2.y;
        a0 += vB * fB0.x; a1 += vB * fB0.y;
        i0 += vB * fB1.x; i1 += vB * fB1.y;
        t0 += vB * fB2.x; t1 += vB * fB2.y;
    }
    if (k < e) {
        int2  ed = __ldg(&g_edge[k]);
        float v  = __int_as_float(ed.y);
        const __half2* xr = (const __half2*)(A + (size_t)ed.x * FDIM);
        float2 f0 = __half22float2(xr[lane]);
        float2 f1 = __half22float2(xr[32 + lane]);
        float2 f2 = __half22float2(xr[64 + lane]);
        a0 += v * f0.x; a1 += v * f0.y;
        i0 += v * f1.x; i1 += v * f1.y;
        t0 += v * f2.x; t1 += v * f2.y;
    }
    int doff = lane * 2;
    float2 bi = *(const float2*)(bias_i + doff);
    float2 bt = *(const float2*)(bias_t + doff);
    __half2* br = (__half2*)(B + (size_t)row * FDIM);
    br[lane]      = __floats2half2_rn(a0, a1);
    br[32 + lane] = __floats2half2_rn(i0 + bi.x, i1 + bi.y);
    br[64 + lane] = __floats2half2_rn(t0 + bt.x, t1 + bt.y);
}

// ---------------- SPMM1 (dense) + need-marker trailing blocks -------------------
#define SPMM_BLOCKS ((NN * 32 + 255) / 256)     // 12500
#define MARK_BLOCKS ((3 * BATCH) / 8)           // 1536 (one warp per target row)

__global__ void k_spmm_mark(const __half* __restrict__ A, __half* __restrict__ B,
                            const float* __restrict__ bias_i, const float* __restrict__ bias_t,
                            const int* __restrict__ uidx, const int* __restrict__ pidx,
                            const int* __restrict__ nidx) {
    int lane = threadIdx.x & 31;
    if (blockIdx.x >= SPMM_BLOCKS) {
        int warp = ((blockIdx.x - SPMM_BLOCKS) * blockDim.x + threadIdx.x) >> 5;
        int g = warp / BATCH;
        int i = warp - g * BATCH;
        int idx = (g == 0) ? __ldg(&uidx[i]) : (g == 1) ? __ldg(&pidx[i]) : __ldg(&nidx[i]);
        int row = (g == 0) ? idx : (N_USERS + idx);
        if (lane == 0) g_needflag[row] = 1;
        int s = g_rowstart[row];
        int e = g_rowstart[row + 1];
        for (int k = s + lane; k < e; k += 32)
            g_needflag[g_edge[k].x] = 1;
        return;
    }
    int warp = (blockIdx.x * blockDim.x + threadIdx.x) >> 5;
    if (warp >= NN) return;
    spmm_row(warp, lane, A, B, bias_i, bias_t);
}

// ---------------- SPMM2 (filtered by needflag) ---------------------------------
__global__ void k_spmm_filt(const __half* __restrict__ A, __half* __restrict__ B,
                            const float* __restrict__ bias_i, const float* __restrict__ bias_t) {
    int warp = (blockIdx.x * blockDim.x + threadIdx.x) >> 5;
    int lane = threadIdx.x & 31;
    if (warp >= NN) return;
    if (g_needflag[warp] == 0) return;
    spmm_row(warp, lane, A, B, bias_i, bias_t);
}

// ---------------- final: on-the-fly layer-3 + sum + mean + l2 + gathers -------
#define FIN_BLOCKS ((3 * BATCH * 32 + 255) / 256)          // 1536
#define ZERO_N     (2 * NN + 256)                          // count + needflag + scanflags
#define ZERO_BLOCKS ((ZERO_N + 255) / 256)                 // 783

__global__ void k_final(const int* __restrict__ uidx, const int* __restrict__ pidx,
                        const int* __restrict__ nidx,
                        const float* __restrict__ bias_i, const float* __restrict__ bias_t,
                        float* __restrict__ out) {
    if (blockIdx.x >= FIN_BLOCKS) {
        int i = (blockIdx.x - FIN_BLOCKS) * 256 + threadIdx.x;
        if (i < NN) g_count[i] = 0;
        else if (i < 2 * NN) g_needflag[i - NN] = 0;
        else if (i < ZERO_N) g_scanflag[i - 2 * NN] = 0;
        return;
    }
    int warp = (blockIdx.x * blockDim.x + threadIdx.x) >> 5;
    int lane = threadIdx.x & 31;
    int g = warp / BATCH;
    int i = warp - g * BATCH;
    int idx = (g == 0) ? __ldg(&uidx[i]) : (g == 1) ? __ldg(&pidx[i]) : __ldg(&nidx[i]);
    int row = (g == 0) ? idx : (N_USERS + idx);

    // hoist stored-layer row loads
    size_t base = (size_t)row * FDIM;
    const __half2* r0 = (const __half2*)(g_F0 + base);
    const __half2* r1 = (const __half2*)(g_F1 + base);
    const __half2* r2 = (const __half2*)(g_F2 + base);
    __half2 h00 = r0[lane],      h01 = r0[32 + lane], h02 = r0[64 + lane];
    __half2 h10 = r1[lane],      h11 = r1[32 + lane], h12 = r1[64 + lane];
    __half2 h20 = r2[lane],      h21 = r2[32 + lane], h22 = r2[64 + lane];

    // ---- layer-3 propagation on the fly from F2 (fp32 accum), unrolled x4 ----
    int s = g_rowstart[row];
    int e = g_rowstart[row + 1];
    float a0 = 0.f, a1 = 0.f, i0 = 0.f, i1 = 0.f, t0 = 0.f, t1 = 0.f;
    int k = s;
    for (; k + 3 < e; k += 4) {
        int2 eA = __ldg(&g_edge[k]);
        int2 eB = __ldg(&g_edge[k + 1]);
        int2 eC = __ldg(&g_edge[k + 2]);
        int2 eD = __ldg(&g_edge[k + 3]);
        const __half2* xA = (const __half2*)(g_F2 + (size_t)eA.x * FDIM);
        const __half2* xB = (const __half2*)(g_F2 + (size_t)eB.x * FDIM);
        const __half2* xC = (const __half2*)(g_F2 + (size_t)eC.x * FDIM);
        const __half2* xD = (const __half2*)(g_F2 + (size_t)eD.x * FDIM);
        float vA = __int_as_float(eA.y), vB = __int_as_float(eB.y);
        float vC = __int_as_float(eC.y), vD = __int_as_float(eD.y);
        float2 fA0 = __half22float2(xA[lane]), fA1 = __half22float2(xA[32 + lane]), fA2 = __half22float2(xA[64 + lane]);
        float2 fB0 = __half22float2(xB[lane]), fB1 = __half22float2(xB[32 + lane]), fB2 = __half22float2(xB[64 + lane]);
        float2 fC0 = __half22float2(xC[lane]), fC1 = __half22float2(xC[32 + lane]), fC2 = __half22float2(xC[64 + lane]);
        float2 fD0 = __half22float2(xD[lane]), fD1 = __half22float2(xD[32 + lane]), fD2 = __half22float2(xD[64 + lane]);
        a0 += vA * fA0.x + vB * fB0.x + vC * fC0.x + vD * fD0.x;
        a1 += vA * fA0.y + vB * fB0.y + vC * fC0.y + vD * fD0.y;
        i0 += vA * fA1.x + vB * fB1.x + vC * fC1.x + vD * fD1.x;
        i1 += vA * fA1.y + vB * fB1.y + vC * fC1.y + vD * fD1.y;
        t0 += vA * fA2.x + vB * fB2.x + vC * fC2.x + vD * fD2.x;
        t1 += vA * fA2.y + vB * fB2.y + vC * fC2.y + vD * fD2.y;
    }
    for (; k < e; k++) {
        int2  ed = __ldg(&g_edge[k]);
        float v  = __int_as_float(ed.y);
        const __half2* xr = (const __half2*)(g_F2 + (size_t)ed.x * FDIM);
        float2 f0 = __half22float2(xr[lane]);
        float2 f1 = __half22float2(xr[32 + lane]);
        float2 f2 = __half22float2(xr[64 + lane]);
        a0 += v * f0.x; a1 += v * f0.y;
        i0 += v * f1.x; i1 += v * f1.y;
        t0 += v * f2.x; t1 += v * f2.y;
    }
    int doff = lane * 2;
    float2 bi = *(const float2*)(bias_i + doff);
    float2 bt = *(const float2*)(bias_t + doff);
    i0 += bi.x; i1 += bi.y;
    t0 += bt.x; t1 += bt.y;

    const float inv = 0.25f;
    float2 me, mi, mt;
    {
        float2 a = __half22float2(h00), b = __half22float2(h10), c = __half22float2(h20);
        me.x = (a.x + b.x + c.x + a0) * inv;  me.y = (a.y + b.y + c.y + a1) * inv;
    }
    {
        float2 a = __half22float2(h01), b = __half22float2(h11), c = __half22float2(h21);
        mi.x = (a.x + b.x + c.x + i0) * inv;  mi.y = (a.y + b.y + c.y + i1) * inv;
    }
    {
        float2 a = __half22float2(h02), b = __half22float2(h12), c = __half22float2(h22);
        mt.x = (a.x + b.x + c.x + t0) * inv;  mt.y = (a.y + b.y + c.y + t1) * inv;
    }

    float sqi = mi.x * mi.x + mi.y * mi.y;
    float sqt = mt.x * mt.x + mt.y * mt.y;
    #pragma unroll
    for (int off = 16; off > 0; off >>= 1) {
        sqi += __shfl_xor_sync(0xFFFFFFFFu, sqi, off);
        sqt += __shfl_xor_sync(0xFFFFFFFFu, sqt, off);
    }
    float si = CAT_RATE / fmaxf(sqrtf(sqi), 1e-12f);
    float st = CAT_RATE / fmaxf(sqrtf(sqt), 1e-12f);

    float2 oe;
    oe.x = me.x + si * mi.x + st * mt.x;
    oe.y = me.y + si * mi.y + st * mt.y;

    size_t slot = (size_t)i * EMBED + doff;
    size_t grp  = (size_t)BATCH * EMBED;
    *(float2*)(out + (size_t)g * grp + slot)       = oe;
    *(float2*)(out + (size_t)(3 + g) * grp + slot) = mi;
    *(float2*)(out + (size_t)(6 + g) * grp + slot) = mt;
}

// ---------------- launch ------------------------------------------------------
extern "C" void kernel_launch(void* const* d_in, const int* in_sizes, int n_in,
                              void* d_out, int out_size) {
    const int*   uidx   = (const int*)  d_in[0];
    const int*   pidx   = (const int*)  d_in[1];
    const int*   nidx   = (const int*)  d_in[2];
    const int*   arows  = (const int*)  d_in[3];
    const int*   acols  = (const int*)  d_in[4];
    const float* avals  = (const float*)d_in[5];
    const float* E0     = (const float*)d_in[6];
    const float* Wimg   = (const float*)d_in[7];
    const float* Bimg   = (const float*)d_in[8];
    const float* Wtxt   = (const float*)d_in[9];
    const float* Btxt   = (const float*)d_in[10];
    float* out = (float*)d_out;

    __half *F0, *F1, *F2;
    cudaGetSymbolAddress((void**)&F0, g_F0);
    cudaGetSymbolAddress((void**)&F1, g_F1);
    cudaGetSymbolAddress((void**)&F2, g_F2);

    // histogram + packed ranks (8 edges/thread)
    k_hist<<<NB_HIST, 256>>>(arows);

    // single-pass CSR offsets (decoupled lookback)
    k_scan<<<SCAN_NB, SCAN_T>>>();

    // striped scatter (4 edges/thread, 1:9) + feature init — best-known packing
    k_scatter_init<<<SI_GRID, 256>>>(arows, acols, avals, E0, Wimg, Wtxt);

    // layer 1 (dense) + needflag marker; layer 2 filtered to needed rows
    k_spmm_mark<<<SPMM_BLOCKS + MARK_BLOCKS, 256>>>(F0, F1, Bimg, Btxt, uidx, pidx, nidx);
    k_spmm_filt<<<SPMM_BLOCKS, 256>>>(F1, F2, Bimg, Btxt);

    // final: on-the-fly layer 3 + sum/mean/normalize/gather (+ scratch resets)
    k_final<<<FIN_BLOCKS + ZERO_BLOCKS, 256>>>(uidx, pidx, nidx, Bimg, Btxt, out);
}

// round 13
// speedup vs baseline: 1.0408x; 1.0408x over previous
#include <cuda_runtime.h>
#include <cuda_fp16.h>

#define N_USERS 50000
#define NN      100000        // total nodes
#define EMBED   64
#define FDIM    192           // 3 streams interleaved: [e | img | txt]
#define NEDGES  1600000
#define BATCH   4096
#define CAT_RATE 0.02f

// ---------------- device scratch ----------------------------------------------
__device__ __half g_F0[NN * FDIM];
__device__ __half g_F1[NN * FDIM];
__device__ __half g_F2[NN * FDIM];
__device__ int           g_count[NN];       // zero at load; re-zeroed each launch
__device__ int           g_rowstart[NN + 1];
__device__ unsigned char g_rank8[NEDGES];   // within-row rank (max deg << 256)
__device__ int           g_needflag[NN];    // rows needing F2; re-zeroed each launch
__device__ int2          g_edge[NEDGES];    // (col, val-as-int-bits), row-grouped
__device__ int           g_blocksums[256];

// ---------------- pure hist (+packed rank), 8 edges/thread ---------------------
#define NB_HIST ((NEDGES / 8 + 255) / 256)      // 782

__global__ void k_hist(const int* __restrict__ rows) {
    int e8 = (blockIdx.x * blockDim.x + threadIdx.x) * 8;
    if (e8 < NEDGES) {
        int4 ra = *(const int4*)(rows + e8);
        int4 rb = *(const int4*)(rows + e8 + 4);
        unsigned int k0 = atomicAdd(&g_count[ra.x], 1);
        unsigned int k1 = atomicAdd(&g_count[ra.y], 1);
        unsigned int k2 = atomicAdd(&g_count[ra.z], 1);
        unsigned int k3 = atomicAdd(&g_count[ra.w], 1);
        unsigned int k4 = atomicAdd(&g_count[rb.x], 1);
        unsigned int k5 = atomicAdd(&g_count[rb.y], 1);
        unsigned int k6 = atomicAdd(&g_count[rb.z], 1);
        unsigned int k7 = atomicAdd(&g_count[rb.w], 1);
        uint2 packed;
        packed.x = (k0 & 0xFF) | ((k1 & 0xFF) << 8) | ((k2 & 0xFF) << 16) | ((k3 & 0xFF) << 24);
        packed.y = (k4 & 0xFF) | ((k5 & 0xFF) << 8) | ((k6 & 0xFF) << 16) | ((k7 & 0xFF) << 24);
        *(uint2*)(g_rank8 + e8) = packed;
    }
}

// ---------------- scan (NN elements), two-pass (R10-proven) --------------------
#define SCAN_T 512
#define SCAN_NB ((NN + SCAN_T - 1) / SCAN_T)   // 196

__global__ void k_scan_p1() {   // raw per-block sums
    __shared__ int sm[SCAN_T];
    int i = blockIdx.x * SCAN_T + threadIdx.x;
    sm[threadIdx.x] = (i < NN) ? g_count[i] : 0;
    __syncthreads();
    for (int off = SCAN_T / 2; off > 0; off >>= 1) {
        if (threadIdx.x < off) sm[threadIdx.x] += sm[threadIdx.x + off];
        __syncthreads();
    }
    if (threadIdx.x == 0) g_blocksums[blockIdx.x] = sm[0];
}

__global__ void k_scan_p3() {   // per-block: prefix of blocksums + local scan
    __shared__ int sm[SCAN_T];
    __shared__ int s_off;
    int contrib = (threadIdx.x < blockIdx.x) ? g_blocksums[threadIdx.x] : 0;
    sm[threadIdx.x] = contrib;
    __syncthreads();
    for (int off = SCAN_T / 2; off > 0; off >>= 1) {
        if (threadIdx.x < off) sm[threadIdx.x] += sm[threadIdx.x + off];
        __syncthreads();
    }
    if (threadIdx.x == 0) s_off = sm[0];
    __syncthreads();
    int i = blockIdx.x * SCAN_T + threadIdx.x;
    int v = (i < NN) ? g_count[i] : 0;
    sm[threadIdx.x] = v;
    __syncthreads();
    for (int off = 1; off < SCAN_T; off <<= 1) {
        int add = (threadIdx.x >= off) ? sm[threadIdx.x - off] : 0;
        __syncthreads();
        sm[threadIdx.x] += add;
        __syncthreads();
    }
    int excl = sm[threadIdx.x] - v + s_off;
    if (i < NN) g_rowstart[i] = excl;
    if (i == 0) g_rowstart[NN] = NEDGES;
}

// ---------------- fused: scatter (4 edges/thread) + feature init, 1:9 stripe ---
#define NB_SCAT  ((NEDGES / 4 + 255) / 256)      // 1563
#define NB_INITE ((NN * EMBED / 4 + 255) / 256)  // 6250
#define NB_TILES (NN / 32)                       // 3125
#define NB_INIT  (NB_INITE + 2 * NB_TILES)       // 12500
#define SI_GRID  (NB_SCAT * 9)                   // 14067: g%9==0 -> scatter

__global__ void k_scatter_init(const int* __restrict__ rows, const int* __restrict__ cols,
                               const float* __restrict__ vals,
                               const float* __restrict__ E0,
                               const float* __restrict__ Wimg,
                               const float* __restrict__ Wtxt) {
    __shared__ float sm[64][33];
    int g = blockIdx.x;
    if (g % 9 == 0) {
        int sb = g / 9;                          // 0..1562
        int e4 = (sb * 256 + threadIdx.x) * 4;
        if (e4 < NEDGES) {
            int4   r4 = *(const int4*)(rows + e4);
            int4   c4 = *(const int4*)(cols + e4);
            float4 v4 = *(const float4*)(vals + e4);
            unsigned int kk = *(const unsigned int*)(g_rank8 + e4);
            g_edge[g_rowstart[r4.x] + ( kk        & 0xFF)] = make_int2(c4.x, __float_as_int(v4.x));
            g_edge[g_rowstart[r4.y] + ((kk >>  8) & 0xFF)] = make_int2(c4.y, __float_as_int(v4.y));
            g_edge[g_rowstart[r4.z] + ((kk >> 16) & 0xFF)] = make_int2(c4.z, __float_as_int(v4.z));
            g_edge[g_rowstart[r4.w] + ((kk >> 24) & 0xFF)] = make_int2(c4.w, __float_as_int(v4.w));
        }
        return;
    }
    int b = g - (g / 9) - 1;                     // contiguous over non-scatter blocks
    if (b >= NB_INIT) return;
    if (b < NB_INITE) {
        int i = b * 256 + threadIdx.x;           // over NN*16 float4s
        if (i < NN * (EMBED / 4)) {
            int n  = i >> 4;
            int d4 = (i & 15) * 4;
            float4 v = ((const float4*)E0)[i];
            __half2* dst = (__half2*)(g_F0 + (size_t)n * FDIM + d4);
            dst[0] = __floats2half2_rn(v.x, v.y);
            dst[1] = __floats2half2_rn(v.z, v.w);
        }
        return;
    }
    b -= NB_INITE;
    const float* W = (b < NB_TILES) ? Wimg : Wtxt;
    int plane_off  = (b < NB_TILES) ? 64 : 128;
    int tile = (b < NB_TILES) ? b : (b - NB_TILES);
    int n0 = tile * 32;
    int tx = threadIdx.x & 31;
    int ty = threadIdx.x >> 5;   // 0..7
    #pragma unroll
    for (int k = 0; k < 8; k++) {
        int d = k * 8 + ty;
        sm[d][tx] = W[(size_t)d * NN + n0 + tx];
    }
    __syncthreads();
    #pragma unroll
    for (int k = 0; k < 4; k++) {
        int row = k * 8 + ty;
        int n = n0 + row;
        #pragma unroll
        for (int dk = 0; dk < 2; dk++) {
            int d = dk * 32 + tx;
            g_F0[(size_t)n * FDIM + plane_off + d] = __float2half_rn(sm[d][row]);
        }
    }
}

// ---------------- SPMM row body: 4 edges in flight (fp32 accum) ----------------
__device__ __forceinline__ void spmm_row(int row, int lane,
                                         const __half* __restrict__ A, __half* __restrict__ B,
                                         const float* __restrict__ bias_i,
                                         const float* __restrict__ bias_t) {
    int s = g_rowstart[row];
    int e = g_rowstart[row + 1];
    float a0 = 0.f, a1 = 0.f, i0 = 0.f, i1 = 0.f, t0 = 0.f, t1 = 0.f;
    int k = s;
    for (; k + 3 < e; k += 4) {
        int2 eA = __ldg(&g_edge[k]);
        int2 eB = __ldg(&g_edge[k + 1]);
        int2 eC = __ldg(&g_edge[k + 2]);
        int2 eD = __ldg(&g_edge[k + 3]);
        const __half2* xA = (const __half2*)(A + (size_t)eA.x * FDIM);
        const __half2* xB = (const __half2*)(A + (size_t)eB.x * FDIM);
        const __half2* xC = (const __half2*)(A + (size_t)eC.x * FDIM);
        const __half2* xD = (const __half2*)(A + (size_t)eD.x * FDIM);
        float vA = __int_as_float(eA.y), vB = __int_as_float(eB.y);
        float vC = __int_as_float(eC.y), vD = __int_as_float(eD.y);
        // issue all 12 loads before any convert/FMA (compiler batches LDGs)
        __half2 hA0 = xA[lane], hA1 = xA[32 + lane], hA2 = xA[64 + lane];
        __half2 hB0 = xB[lane], hB1 = xB[32 + lane], hB2 = xB[64 + lane];
        __half2 hC0 = xC[lane], hC1 = xC[32 + lane], hC2 = xC[64 + lane];
        __half2 hD0 = xD[lane], hD1 = xD[32 + lane], hD2 = xD[64 + lane];
        float2 f;
        f = __half22float2(hA0); a0 += vA * f.x; a1 += vA * f.y;
        f = __half22float2(hA1); i0 += vA * f.x; i1 += vA * f.y;
        f = __half22float2(hA2); t0 += vA * f.x; t1 += vA * f.y;
        f = __half22float2(hB0); a0 += vB * f.x; a1 += vB * f.y;
        f = __half22float2(hB1); i0 += vB * f.x; i1 += vB * f.y;
        f = __half22float2(hB2); t0 += vB * f.x; t1 += vB * f.y;
        f = __half22float2(hC0); a0 += vC * f.x; a1 += vC * f.y;
        f = __half22float2(hC1); i0 += vC * f.x; i1 += vC * f.y;
        f = __half22float2(hC2); t0 += vC * f.x; t1 += vC * f.y;
        f = __half22float2(hD0); a0 += vD * f.x; a1 += vD * f.y;
        f = __half22float2(hD1); i0 += vD * f.x; i1 += vD * f.y;
        f = __half22float2(hD2); t0 += vD * f.x; t1 += vD * f.y;
    }
    for (; k < e; k++) {
        int2  ed = __ldg(&g_edge[k]);
        float v  = __int_as_float(ed.y);
        const __half2* xr = (const __half2*)(A + (size_t)ed.x * FDIM);
        float2 f0 = __half22float2(xr[lane]);
        float2 f1 = __half22float2(xr[32 + lane]);
        float2 f2 = __half22float2(xr[64 + lane]);
        a0 += v * f0.x; a1 += v * f0.y;
        i0 += v * f1.x; i1 += v * f1.y;
        t0 += v * f2.x; t1 += v * f2.y;
    }
    int doff = lane * 2;
    float2 bi = *(const float2*)(bias_i + doff);
    float2 bt = *(const float2*)(bias_t + doff);
    __half2* br = (__half2*)(B + (size_t)row * FDIM);
    br[lane]      = __floats2half2_rn(a0, a1);
    br[32 + lane] = __floats2half2_rn(i0 + bi.x, i1 + bi.y);
    br[64 + lane] = __floats2half2_rn(t0 + bt.x, t1 + bt.y);
}

// ---------------- SPMM1 (dense) + need-marker trailing blocks -------------------
#define SPMM_BLOCKS ((NN * 32 + 255) / 256)     // 12500
#define MARK_BLOCKS ((3 * BATCH) / 8)           // 1536 (one warp per target row)

__global__ void k_spmm_mark(const __half* __restrict__ A, __half* __restrict__ B,
                            const float* __restrict__ bias_i, const float* __restrict__ bias_t,
                            const int* __restrict__ uidx, const int* __restrict__ pidx,
                            const int* __restrict__ nidx) {
    int lane = threadIdx.x & 31;
    if (blockIdx.x >= SPMM_BLOCKS) {
        int warp = ((blockIdx.x - SPMM_BLOCKS) * blockDim.x + threadIdx.x) >> 5;
        int g = warp / BATCH;
        int i = warp - g * BATCH;
        int idx = (g == 0) ? __ldg(&uidx[i]) : (g == 1) ? __ldg(&pidx[i]) : __ldg(&nidx[i]);
        int row = (g == 0) ? idx : (N_USERS + idx);
        if (lane == 0) g_needflag[row] = 1;
        int s = g_rowstart[row];
        int e = g_rowstart[row + 1];
        for (int k = s + lane; k < e; k += 32)
            g_needflag[g_edge[k].x] = 1;
        return;
    }
    int warp = (blockIdx.x * blockDim.x + threadIdx.x) >> 5;
    if (warp >= NN) return;
    spmm_row(warp, lane, A, B, bias_i, bias_t);
}

// ---------------- SPMM2 (filtered by needflag) ---------------------------------
__global__ void k_spmm_filt(const __half* __restrict__ A, __half* __restrict__ B,
                            const float* __restrict__ bias_i, const float* __restrict__ bias_t) {
    int warp = (blockIdx.x * blockDim.x + threadIdx.x) >> 5;
    int lane = threadIdx.x & 31;
    if (warp >= NN) return;
    if (g_needflag[warp] == 0) return;
    spmm_row(warp, lane, A, B, bias_i, bias_t);
}

// ---------------- final: on-the-fly layer-3 + sum + mean + l2 + gathers -------
#define FIN_BLOCKS ((3 * BATCH * 32 + 255) / 256)          // 1536
#define ZERO_N     (2 * NN)                                // count + needflag
#define ZERO_BLOCKS ((ZERO_N + 255) / 256)                 // 782

__global__ void k_final(const int* __restrict__ uidx, const int* __restrict__ pidx,
                        const int* __restrict__ nidx,
                        const float* __restrict__ bias_i, const float* __restrict__ bias_t,
                        float* __restrict__ out) {
    if (blockIdx.x >= FIN_BLOCKS) {
        int i = (blockIdx.x - FIN_BLOCKS) * 256 + threadIdx.x;
        if (i < NN) g_count[i] = 0;
        else if (i < 2 * NN) g_needflag[i - NN] = 0;
        return;
    }
    int warp = (blockIdx.x * blockDim.x + threadIdx.x) >> 5;
    int lane = threadIdx.x & 31;
    int g = warp / BATCH;
    int i = warp - g * BATCH;
    int idx = (g == 0) ? __ldg(&uidx[i]) : (g == 1) ? __ldg(&pidx[i]) : __ldg(&nidx[i]);
    int row = (g == 0) ? idx : (N_USERS + idx);

    // hoist stored-layer row loads: independent of the edge-gather chain
    size_t base = (size_t)row * FDIM;
    const __half2* r0 = (const __half2*)(g_F0 + base);
    const __half2* r1 = (const __half2*)(g_F1 + base);
    const __half2* r2 = (const __half2*)(g_F2 + base);
    __half2 h00 = r0[lane],      h01 = r0[32 + lane], h02 = r0[64 + lane];
    __half2 h10 = r1[lane],      h11 = r1[32 + lane], h12 = r1[64 + lane];
    __half2 h20 = r2[lane],      h21 = r2[32 + lane], h22 = r2[64 + lane];

    // ---- layer-3 propagation on the fly from F2 (fp32 accum), unrolled x2 ----
    int s = g_rowstart[row];
    int e = g_rowstart[row + 1];
    float a0 = 0.f, a1 = 0.f, i0 = 0.f, i1 = 0.f, t0 = 0.f, t1 = 0.f;
    int k = s;
    for (; k + 1 < e; k += 2) {
        int2  eA = __ldg(&g_edge[k]);
        int2  eB = __ldg(&g_edge[k + 1]);
        float vA = __int_as_float(eA.y);
        float vB = __int_as_float(eB.y);
        const __half2* xA = (const __half2*)(g_F2 + (size_t)eA.x * FDIM);
        const __half2* xB = (const __half2*)(g_F2 + (size_t)eB.x * FDIM);
        float2 fA0 = __half22float2(xA[lane]);
        float2 fA1 = __half22float2(xA[32 + lane]);
        float2 fA2 = __half22float2(xA[64 + lane]);
        float2 fB0 = __half22float2(xB[lane]);
        float2 fB1 = __half22float2(xB[32 + lane]);
        float2 fB2 = __half22float2(xB[64 + lane]);
        a0 += vA * fA0.x; a1 += vA * fA0.y;
        i0 += vA * fA1.x; i1 += vA * fA1.y;
        t0 += vA * fA2.x; t1 += vA * fA2.y;
        a0 += vB * fB0.x; a1 += vB * fB0.y;
        i0 += vB * fB1.x; i1 += vB * fB1.y;
        t0 += vB * fB2.x; t1 += vB * fB2.y;
    }
    if (k < e) {
        int2  ed = __ldg(&g_edge[k]);
        float v  = __int_as_float(ed.y);
        const __half2* xr = (const __half2*)(g_F2 + (size_t)ed.x * FDIM);
        float2 f0 = __half22float2(xr[lane]);
        float2 f1 = __half22float2(xr[32 + lane]);
        float2 f2 = __half22float2(xr[64 + lane]);
        a0 += v * f0.x; a1 += v * f0.y;
        i0 += v * f1.x; i1 += v * f1.y;
        t0 += v * f2.x; t1 += v * f2.y;
    }
    int doff = lane * 2;
    float2 bi = *(const float2*)(bias_i + doff);
    float2 bt = *(const float2*)(bias_t + doff);
    i0 += bi.x; i1 += bi.y;
    t0 += bt.x; t1 += bt.y;

    const float inv = 0.25f;
    float2 me, mi, mt;
    {
        float2 a = __half22float2(h00), b = __half22float2(h10), c = __half22float2(h20);
        me.x = (a.x + b.x + c.x + a0) * inv;  me.y = (a.y + b.y + c.y + a1) * inv;
    }
    {
        float2 a = __half22float2(h01), b = __half22float2(h11), c = __half22float2(h21);
        mi.x = (a.x + b.x + c.x + i0) * inv;  mi.y = (a.y + b.y + c.y + i1) * inv;
    }
    {
        float2 a = __half22float2(h02), b = __half22float2(h12), c = __half22float2(h22);
        mt.x = (a.x + b.x + c.x + t0) * inv;  mt.y = (a.y + b.y + c.y + t1) * inv;
    }

    float sqi = mi.x * mi.x + mi.y * mi.y;
    float sqt = mt.x * mt.x + mt.y * mt.y;
    #pragma unroll
    for (int off = 16; off > 0; off >>= 1) {
        sqi += __shfl_xor_sync(0xFFFFFFFFu, sqi, off);
        sqt += __shfl_xor_sync(0xFFFFFFFFu, sqt, off);
    }
    float si = CAT_RATE / fmaxf(sqrtf(sqi), 1e-12f);
    float st = CAT_RATE / fmaxf(sqrtf(sqt), 1e-12f);

    float2 oe;
    oe.x = me.x + si * mi.x + st * mt.x;
    oe.y = me.y + si * mi.y + st * mt.y;

    size_t slot = (size_t)i * EMBED + doff;
    size_t grp  = (size_t)BATCH * EMBED;
    *(float2*)(out + (size_t)g * grp + slot)       = oe;
    *(float2*)(out + (size_t)(3 + g) * grp + slot) = mi;
    *(float2*)(out + (size_t)(6 + g) * grp + slot) = mt;
}

// ---------------- launch ------------------------------------------------------
extern "C" void kernel_launch(void* const* d_in, const int* in_sizes, int n_in,
                              void* d_out, int out_size) {
    const int*   uidx   = (const int*)  d_in[0];
    const int*   pidx   = (const int*)  d_in[1];
    const int*   nidx   = (const int*)  d_in[2];
    const int*   arows  = (const int*)  d_in[3];
    const int*   acols  = (const int*)  d_in[4];
    const float* avals  = (const float*)d_in[5];
    const float* E0     = (const float*)d_in[6];
    const float* Wimg   = (const float*)d_in[7];
    const float* Bimg   = (const float*)d_in[8];
    const float* Wtxt   = (const float*)d_in[9];
    const float* Btxt   = (const float*)d_in[10];
    float* out = (float*)d_out;

    __half *F0, *F1, *F2;
    cudaGetSymbolAddress((void**)&F0, g_F0);
    cudaGetSymbolAddress((void**)&F1, g_F1);
    cudaGetSymbolAddress((void**)&F2, g_F2);

    // histogram + packed ranks (8 edges/thread)
    k_hist<<<NB_HIST, 256>>>(arows);

    // CSR offsets (two-pass, R10-proven)
    k_scan_p1<<<SCAN_NB, SCAN_T>>>();
    k_scan_p3<<<SCAN_NB, SCAN_T>>>();

    // striped scatter (4 edges/thread, 1:9) + feature init — best-known packing
    k_scatter_init<<<SI_GRID, 256>>>(arows, acols, avals, E0, Wimg, Wtxt);

    // layer 1 (dense, unroll-4) + needflag marker; layer 2 filtered
    k_spmm_mark<<<SPMM_BLOCKS + MARK_BLOCKS, 256>>>(F0, F1, Bimg, Btxt, uidx, pidx, nidx);
    k_spmm_filt<<<SPMM_BLOCKS, 256>>>(F1, F2, Bimg, Btxt);

    // final: on-the-fly layer 3 + sum/mean/normalize/gather (+ scratch resets)
    k_final<<<FIN_BLOCKS + ZERO_BLOCKS, 256>>>(uidx, pidx, nidx, Bimg, Btxt, out);
}